// round 9
// baseline (speedup 1.0000x reference)
#include <cuda_runtime.h>
#include <cuda_bf16.h>
#include <mma.h>

using namespace nvcuda;

#define BB 4
#define CC 128
#define NN 4096
#define LDH 136   // bf16 tile leading dim (pad 8)
#define LDF 132   // fp32 tile leading dim (pad 4)

typedef wmma::fragment<wmma::matrix_a,16,16,16,__nv_bfloat16,wmma::row_major> FragA;
typedef wmma::fragment<wmma::matrix_b,16,16,16,__nv_bfloat16,wmma::col_major> FragBc;
typedef wmma::fragment<wmma::matrix_b,16,16,16,__nv_bfloat16,wmma::row_major> FragBr;
typedef wmma::fragment<wmma::accumulator,16,16,16,float> FragC;

// ---------------- device scratch (static allocation: allowed) ----------------
__device__ __nv_bfloat16 d_wqkv[3*CC*CC];
__device__ __nv_bfloat16 d_wproj[CC*CC];
__device__ float d_scl[BB*CC];   // per (b,c) scale  = rstd*gamma
__device__ float d_sht[BB*CC];   // per (b,c) shift  = beta - mean*rstd*gamma
__device__ __nv_bfloat16 d_q[BB*NN*CC];
__device__ __nv_bfloat16 d_k[BB*NN*CC];
__device__ __nv_bfloat16 d_v[BB*NN*CC];
__device__ __nv_bfloat16 d_o[BB*NN*CC];

// ---------------- K0: convert weights to bf16 ----------------
__global__ __launch_bounds__(256) void k_convert(const float* __restrict__ qkvw,
                                                 const float* __restrict__ projw) {
    int i = blockIdx.x*256 + threadIdx.x;
    if (i < 3*CC*CC) d_wqkv[i]  = __float2bfloat16(qkvw[i]);
    if (i < CC*CC)   d_wproj[i] = __float2bfloat16(projw[i]);
}

// ---------------- K1: GroupNorm stats -> per-channel scale/shift ----------------
__global__ __launch_bounds__(256) void k_gnstats(const float* __restrict__ x,
                                                 const float* __restrict__ nw,
                                                 const float* __restrict__ nb) {
    int b = blockIdx.x >> 3, g = blockIdx.x & 7;
    const float4* p = (const float4*)(x + ((size_t)(b*CC) + g*16)*NN);
    const int M4 = (16*NN)/4;   // contiguous span (channels contiguous within group)
    float s = 0.f, s2 = 0.f;
    for (int i = threadIdx.x; i < M4; i += 256) {
        float4 v = p[i];
        s  += v.x + v.y + v.z + v.w;
        s2 += v.x*v.x + v.y*v.y + v.z*v.z + v.w*v.w;
    }
    __shared__ float rs[8], rs2[8];
    #pragma unroll
    for (int o = 16; o; o >>= 1) {
        s  += __shfl_xor_sync(0xffffffffu, s,  o);
        s2 += __shfl_xor_sync(0xffffffffu, s2, o);
    }
    if ((threadIdx.x & 31) == 0) { rs[threadIdx.x>>5] = s; rs2[threadIdx.x>>5] = s2; }
    __syncthreads();
    __shared__ float smean, srstd;
    if (threadIdx.x == 0) {
        float ts = 0.f, ts2 = 0.f;
        #pragma unroll
        for (int i = 0; i < 8; i++) { ts += rs[i]; ts2 += rs2[i]; }
        const float M = 16.f*NN;
        float mean = ts / M;
        float var  = ts2 / M - mean*mean;
        smean = mean;
        srstd = rsqrtf(var + 1e-5f);
    }
    __syncthreads();
    if (threadIdx.x < 16) {
        int c = g*16 + threadIdx.x;
        float w = nw[c];
        d_scl[b*CC + c] = srstd * w;
        d_sht[b*CC + c] = nb[c] - smean * srstd * w;
    }
}

// ---------------- K2: fused normalize + QKV GEMM ----------------
// per CTA: one (b, n-tile of 128). A = normalized x^T tile [128n x 128c] (bf16),
// loop over 3 output tiles (q,k,v), B = qkv_w [o][c] as col-major K^T.
__global__ __launch_bounds__(256) void k_qkv(const float* __restrict__ x,
                                             const float* __restrict__ qkvb) {
    extern __shared__ char sm[];
    __nv_bfloat16* As = (__nv_bfloat16*)sm;                 // [128][LDH]
    __nv_bfloat16* Bs = As + 128*LDH;                       // [128][LDH]
    float*         Cs = (float*)(Bs + 128*LDH);             // [128][LDF]
    const int nt = blockIdx.x, b = blockIdx.y, tid = threadIdx.x;
    const int nbase = nt*128;

    // load + normalize + transpose A
    {
        int c = tid >> 1, nh = tid & 1;
        const float4* xp = (const float4*)(x + ((size_t)(b*CC) + c)*NN + nbase + nh*64);
        float sc = d_scl[b*CC + c], sh = d_sht[b*CC + c];
        #pragma unroll
        for (int i = 0; i < 16; i++) {
            float4 v = xp[i];
            int n = nh*64 + i*4;
            As[(n+0)*LDH + c] = __float2bfloat16(v.x*sc + sh);
            As[(n+1)*LDH + c] = __float2bfloat16(v.y*sc + sh);
            As[(n+2)*LDH + c] = __float2bfloat16(v.z*sc + sh);
            As[(n+3)*LDH + c] = __float2bfloat16(v.w*sc + sh);
        }
    }

    const int w = tid >> 5, wr = w >> 1, wc = w & 1;
    for (int ot = 0; ot < 3; ot++) {
        __syncthreads();
        // load B tile (row o, contiguous c)
        {
            int o = tid >> 1, ch = tid & 1;
            const uint2* wp = (const uint2*)(d_wqkv + (ot*128 + o)*CC + ch*64);
            uint2* dp = (uint2*)(Bs + o*LDH + ch*64);
            #pragma unroll
            for (int i = 0; i < 16; i++) dp[i] = wp[i];
        }
        __syncthreads();
        #pragma unroll
        for (int i = 0; i < 2; i++) {
            FragC acc[4];
            #pragma unroll
            for (int jj = 0; jj < 4; jj++) wmma::fill_fragment(acc[jj], 0.f);
            #pragma unroll
            for (int k = 0; k < 8; k++) {
                FragA a; wmma::load_matrix_sync(a, As + (wr*32 + i*16)*LDH + k*16, LDH);
                #pragma unroll
                for (int jj = 0; jj < 4; jj++) {
                    FragBc bfr; wmma::load_matrix_sync(bfr, Bs + (wc*64 + jj*16)*LDH + k*16, LDH);
                    wmma::mma_sync(acc[jj], a, bfr, acc[jj]);
                }
            }
            #pragma unroll
            for (int jj = 0; jj < 4; jj++)
                wmma::store_matrix_sync(Cs + (wr*32 + i*16)*LDF + wc*64 + jj*16, acc[jj], LDF, wmma::mem_row_major);
        }
        __syncthreads();
        // write out q/k/v bf16 with bias
        __nv_bfloat16* dst = (ot == 0) ? d_q : (ot == 1) ? d_k : d_v;
        {
            int n = tid >> 1, oh = tid & 1;
            __nv_bfloat16* op = dst + ((size_t)(b*NN) + nbase + n)*CC + oh*64;
            const float* cp = Cs + n*LDF + oh*64;
            const float* bp = qkvb + ot*128 + oh*64;
            #pragma unroll
            for (int i = 0; i < 64; i++) op[i] = __float2bfloat16(cp[i] + bp[i]);
        }
    }
}

// ---------------- K3: attention (no-max softmax, unnormalized accumulate) ----------------
__global__ __launch_bounds__(256) void k_attn() {
    extern __shared__ char sm[];
    __nv_bfloat16* Qs = (__nv_bfloat16*)sm;        // [128][LDH]
    __nv_bfloat16* Ks = Qs + 128*LDH;
    __nv_bfloat16* Vs = Ks + 128*LDH;
    __nv_bfloat16* Ps = Vs + 128*LDH;
    float*         Ss = (float*)(Ps + 128*LDH);    // [128][LDF], reused for O at end
    float*       lsum = Ss + 128*LDF;              // [128]
    float*      lpart = lsum + 128;                // [256]

    const int qt = blockIdx.x, b = blockIdx.y, tid = threadIdx.x;
    const int w = tid >> 5, wr = w >> 1, wc = w & 1;
    const float scale = 0.08838834764831845f;  // 1/sqrt(128)

    // load Q tile (vectorized)
    {
        const uint2* qg = (const uint2*)(d_q + ((size_t)(b*NN) + qt*128)*CC);
        for (int i = tid; i < 128*32; i += 256) {
            int r = i >> 5, c4 = (i & 31)*4;
            *(uint2*)&Qs[r*LDH + c4] = qg[r*32 + (i & 31)];
        }
    }
    if (tid < 128) lsum[tid] = 0.f;

    FragC o_acc[2][4];
    #pragma unroll
    for (int i = 0; i < 2; i++)
        #pragma unroll
        for (int jj = 0; jj < 4; jj++) wmma::fill_fragment(o_acc[i][jj], 0.f);

    for (int kt = 0; kt < 32; kt++) {
        __syncthreads();
        // load K, V tiles
        {
            const uint2* kg = (const uint2*)(d_k + ((size_t)(b*NN) + kt*128)*CC);
            const uint2* vg = (const uint2*)(d_v + ((size_t)(b*NN) + kt*128)*CC);
            for (int i = tid; i < 128*32; i += 256) {
                int r = i >> 5, cv = i & 31;
                *(uint2*)&Ks[r*LDH + cv*4] = kg[r*32 + cv];
                *(uint2*)&Vs[r*LDH + cv*4] = vg[r*32 + cv];
            }
        }
        __syncthreads();
        // S = Q K^T, exp, store to Ss
        #pragma unroll
        for (int i = 0; i < 2; i++) {
            FragC s4[4];
            #pragma unroll
            for (int jj = 0; jj < 4; jj++) wmma::fill_fragment(s4[jj], 0.f);
            #pragma unroll
            for (int k = 0; k < 8; k++) {
                FragA a; wmma::load_matrix_sync(a, Qs + (wr*32 + i*16)*LDH + k*16, LDH);
                #pragma unroll
                for (int jj = 0; jj < 4; jj++) {
                    FragBc bfr; wmma::load_matrix_sync(bfr, Ks + (wc*64 + jj*16)*LDH + k*16, LDH);
                    wmma::mma_sync(s4[jj], a, bfr, s4[jj]);
                }
            }
            #pragma unroll
            for (int jj = 0; jj < 4; jj++) {
                #pragma unroll
                for (int e = 0; e < s4[jj].num_elements; e++)
                    s4[jj].x[e] = __expf(s4[jj].x[e]*scale);
                wmma::store_matrix_sync(Ss + (wr*32 + i*16)*LDF + wc*64 + jj*16, s4[jj], LDF, wmma::mem_row_major);
            }
        }
        __syncthreads();
        // P = bf16(exp), accumulate row sums
        {
            int r = tid >> 1, hh = tid & 1;
            const float* sp = Ss + r*LDF + hh*64;
            __nv_bfloat16* pp = Ps + r*LDH + hh*64;
            float s = 0.f;
            #pragma unroll
            for (int i = 0; i < 32; i++) {
                float v0 = sp[2*i], v1 = sp[2*i+1];
                *(__nv_bfloat162*)&pp[2*i] = __floats2bfloat162_rn(v0, v1);
                s += v0 + v1;
            }
            lpart[tid] = s;
        }
        __syncthreads();
        if (tid < 128) lsum[tid] += lpart[tid*2] + lpart[tid*2 + 1];
        // O += P V
        #pragma unroll
        for (int i = 0; i < 2; i++) {
            #pragma unroll
            for (int k = 0; k < 8; k++) {
                FragA a; wmma::load_matrix_sync(a, Ps + (wr*32 + i*16)*LDH + k*16, LDH);
                #pragma unroll
                for (int jj = 0; jj < 4; jj++) {
                    FragBr bfr; wmma::load_matrix_sync(bfr, Vs + (k*16)*LDH + wc*64 + jj*16, LDH);
                    wmma::mma_sync(o_acc[i][jj], a, bfr, o_acc[i][jj]);
                }
            }
        }
    }
    __syncthreads();
    // stage O to smem, then normalize + write bf16
    #pragma unroll
    for (int i = 0; i < 2; i++)
        #pragma unroll
        for (int jj = 0; jj < 4; jj++)
            wmma::store_matrix_sync(Ss + (wr*32 + i*16)*LDF + wc*64 + jj*16, o_acc[i][jj], LDF, wmma::mem_row_major);
    __syncthreads();
    {
        int r = tid >> 1, hh = tid & 1;
        float inv = 1.f / lsum[r];
        __nv_bfloat16* og = d_o + ((size_t)(b*NN) + qt*128 + r)*CC + hh*64;
        const float* sp = Ss + r*LDF + hh*64;
        #pragma unroll
        for (int i = 0; i < 64; i++) og[i] = __float2bfloat16(sp[i]*inv);
    }
}

// ---------------- K4: proj GEMM + bias + residual ----------------
__global__ __launch_bounds__(256) void k_proj(const float* __restrict__ x,
                                              const float* __restrict__ projb,
                                              float* __restrict__ out) {
    extern __shared__ char sm[];
    __nv_bfloat16* As = (__nv_bfloat16*)sm;                 // [128n][LDH]
    __nv_bfloat16* Bs = As + 128*LDH;                       // [128o][LDH]
    float*         Cs = (float*)(Bs + 128*LDH);             // [128n][LDF]
    const int nt = blockIdx.x, b = blockIdx.y, tid = threadIdx.x;
    const int nbase = nt*128;

    // load A = attention output tile [n][c] bf16
    {
        const uint2* ag = (const uint2*)(d_o + ((size_t)(b*NN) + nbase)*CC);
        for (int i = tid; i < 128*32; i += 256) {
            int r = i >> 5, cv = i & 31;
            *(uint2*)&As[r*LDH + cv*4] = ag[r*32 + cv];
        }
    }
    // load B = proj_w [o][c]
    {
        int o = tid >> 1, ch = tid & 1;
        const uint2* wp = (const uint2*)(d_wproj + o*CC + ch*64);
        uint2* dp = (uint2*)(Bs + o*LDH + ch*64);
        #pragma unroll
        for (int i = 0; i < 16; i++) dp[i] = wp[i];
    }
    __syncthreads();

    const int w = tid >> 5, wr = w >> 1, wc = w & 1;
    #pragma unroll
    for (int i = 0; i < 2; i++) {
        FragC acc[4];
        #pragma unroll
        for (int jj = 0; jj < 4; jj++) wmma::fill_fragment(acc[jj], 0.f);
        #pragma unroll
        for (int k = 0; k < 8; k++) {
            FragA a; wmma::load_matrix_sync(a, As + (wr*32 + i*16)*LDH + k*16, LDH);
            #pragma unroll
            for (int jj = 0; jj < 4; jj++) {
                FragBc bfr; wmma::load_matrix_sync(bfr, Bs + (wc*64 + jj*16)*LDH + k*16, LDH);
                wmma::mma_sync(acc[jj], a, bfr, acc[jj]);
            }
        }
        #pragma unroll
        for (int jj = 0; jj < 4; jj++)
            wmma::store_matrix_sync(Cs + (wr*32 + i*16)*LDF + wc*64 + jj*16, acc[jj], LDF, wmma::mem_row_major);
    }
    __syncthreads();
    // out[b][c][n] = x + proj + bias  (transposed write, coalesced over n)
    {
        int c = tid >> 1, nh = tid & 1;
        const float* xp = x + ((size_t)(b*CC) + c)*NN + nbase + nh*64;
        float* op = out + ((size_t)(b*CC) + c)*NN + nbase + nh*64;
        float pb = projb[c];
        #pragma unroll
        for (int i = 0; i < 64; i++)
            op[i] = xp[i] + pb + Cs[(nh*64 + i)*LDF + c];
    }
}

// ---------------- launcher ----------------
extern "C" void kernel_launch(void* const* d_in, const int* in_sizes, int n_in,
                              void* d_out, int out_size) {
    const float* x     = (const float*)d_in[0];
    const float* nw    = (const float*)d_in[1];
    const float* nb    = (const float*)d_in[2];
    const float* qkvw  = (const float*)d_in[3];
    const float* qkvb  = (const float*)d_in[4];
    const float* projw = (const float*)d_in[5];
    const float* projb = (const float*)d_in[6];
    float* out = (float*)d_out;

    const int SM_GEMM = 2*128*LDH*2 + 128*LDF*4;                       // 137216
    const int SM_ATTN = 4*128*LDH*2 + 128*LDF*4 + (128 + 256)*4;       // 208384

    cudaFuncSetAttribute(k_qkv,  cudaFuncAttributeMaxDynamicSharedMemorySize, SM_GEMM);
    cudaFuncSetAttribute(k_attn, cudaFuncAttributeMaxDynamicSharedMemorySize, SM_ATTN);
    cudaFuncSetAttribute(k_proj, cudaFuncAttributeMaxDynamicSharedMemorySize, SM_GEMM);

    k_convert<<<192, 256>>>(qkvw, projw);
    k_gnstats<<<32, 256>>>(x, nw, nb);
    k_qkv<<<dim3(32, BB), 256, SM_GEMM>>>(x, qkvb);
    k_attn<<<dim3(32, BB), 256, SM_ATTN>>>();
    k_proj<<<dim3(32, BB), 256, SM_GEMM>>>(x, projb, out);
}

// round 11
// speedup vs baseline: 2.2411x; 2.2411x over previous
#include <cuda_runtime.h>
#include <cuda_bf16.h>
#include <mma.h>
#include <cstdint>

using namespace nvcuda;

#define BB 4
#define CC 128
#define NN 4096
#define LDH 136   // bf16 tile leading dim (pad 8)
#define LDF 132   // fp32 tile leading dim (pad 4)

typedef wmma::fragment<wmma::matrix_a,16,16,16,__nv_bfloat16,wmma::row_major> FragA;
typedef wmma::fragment<wmma::matrix_b,16,16,16,__nv_bfloat16,wmma::col_major> FragBc;
typedef wmma::fragment<wmma::accumulator,16,16,16,float> FragC;

// ---------------- device scratch ----------------
__device__ __align__(16) __nv_bfloat16 d_wqkv[3*CC*CC];
__device__ __align__(16) __nv_bfloat16 d_wproj[CC*CC];
__device__ float d_scl[BB*CC];
__device__ float d_sht[BB*CC];
__device__ __align__(16) __nv_bfloat16 d_q[BB*NN*CC];   // [b][n][c]
__device__ __align__(16) __nv_bfloat16 d_k[BB*NN*CC];   // [b][n][c]
__device__ __align__(16) __nv_bfloat16 d_v[BB*NN*CC];   // [b][n][c]
__device__ __align__(16) __nv_bfloat16 d_o[BB*NN*CC];   // [b][n][c]

// ================= low-level helpers (all sm_80-legal) =================
__device__ __forceinline__ uint32_t smem_u32(const void* p) {
    uint32_t a;
    asm("{ .reg .u64 t; cvta.to.shared.u64 t, %1; cvt.u32.u64 %0, t; }" : "=r"(a) : "l"(p));
    return a;
}
__device__ __forceinline__ void cpa16(uint32_t d, const void* s) {
    asm volatile("cp.async.cg.shared.global [%0], [%1], 16;" :: "r"(d), "l"(s));
}
#define CP_COMMIT() asm volatile("cp.async.commit_group;" ::: "memory")
#define CP_WAIT(n)  asm volatile("cp.async.wait_group %0;" :: "n"(n) : "memory")

__device__ __forceinline__ void ldsm4(uint32_t r[4], uint32_t a) {
    asm volatile("ldmatrix.sync.aligned.m8n8.x4.shared.b16 {%0,%1,%2,%3}, [%4];"
        : "=r"(r[0]), "=r"(r[1]), "=r"(r[2]), "=r"(r[3]) : "r"(a));
}
__device__ __forceinline__ void ldsm4t(uint32_t r[4], uint32_t a) {
    asm volatile("ldmatrix.sync.aligned.m8n8.x4.trans.shared.b16 {%0,%1,%2,%3}, [%4];"
        : "=r"(r[0]), "=r"(r[1]), "=r"(r[2]), "=r"(r[3]) : "r"(a));
}
__device__ __forceinline__ void mma16816(float c[4], const uint32_t a[4], const uint32_t b[2]) {
    asm volatile("mma.sync.aligned.m16n8k16.row.col.f32.bf16.bf16.f32 "
        "{%0,%1,%2,%3}, {%4,%5,%6,%7}, {%8,%9}, {%0,%1,%2,%3};"
        : "+f"(c[0]), "+f"(c[1]), "+f"(c[2]), "+f"(c[3])
        : "r"(a[0]), "r"(a[1]), "r"(a[2]), "r"(a[3]), "r"(b[0]), "r"(b[1]));
}
__device__ __forceinline__ float ex2f(float x) {
    float y;
    asm("ex2.approx.f32 %0, %1;" : "=f"(y) : "f"(x));
    return y;
}
__device__ __forceinline__ uint32_t packbf2(float a, float b) {
    __nv_bfloat162 h = __floats2bfloat162_rn(a, b);
    return *(uint32_t*)&h;
}

// ---------------- K0: convert weights to bf16 ----------------
__global__ __launch_bounds__(256) void k_convert(const float* __restrict__ qkvw,
                                                 const float* __restrict__ projw) {
    int i = blockIdx.x*256 + threadIdx.x;
    if (i < 3*CC*CC) d_wqkv[i]  = __float2bfloat16(qkvw[i]);
    if (i < CC*CC)   d_wproj[i] = __float2bfloat16(projw[i]);
}

// ---------------- K1: GroupNorm stats ----------------
__global__ __launch_bounds__(256) void k_gnstats(const float* __restrict__ x,
                                                 const float* __restrict__ nw,
                                                 const float* __restrict__ nb) {
    int b = blockIdx.x >> 3, g = blockIdx.x & 7;
    const float4* p = (const float4*)(x + ((size_t)(b*CC) + g*16)*NN);
    const int M4 = (16*NN)/4;
    float s = 0.f, s2 = 0.f;
    for (int i = threadIdx.x; i < M4; i += 256) {
        float4 v = p[i];
        s  += v.x + v.y + v.z + v.w;
        s2 += v.x*v.x + v.y*v.y + v.z*v.z + v.w*v.w;
    }
    __shared__ float rs[8], rs2[8];
    #pragma unroll
    for (int o = 16; o; o >>= 1) {
        s  += __shfl_xor_sync(0xffffffffu, s,  o);
        s2 += __shfl_xor_sync(0xffffffffu, s2, o);
    }
    if ((threadIdx.x & 31) == 0) { rs[threadIdx.x>>5] = s; rs2[threadIdx.x>>5] = s2; }
    __syncthreads();
    __shared__ float smean, srstd;
    if (threadIdx.x == 0) {
        float ts = 0.f, ts2 = 0.f;
        #pragma unroll
        for (int i = 0; i < 8; i++) { ts += rs[i]; ts2 += rs2[i]; }
        const float M = 16.f*NN;
        float mean = ts / M;
        float var  = ts2 / M - mean*mean;
        smean = mean;
        srstd = rsqrtf(var + 1e-5f);
    }
    __syncthreads();
    if (threadIdx.x < 16) {
        int c = g*16 + threadIdx.x;
        float w = nw[c];
        d_scl[b*CC + c] = srstd * w;
        d_sht[b*CC + c] = nb[c] - smean * srstd * w;
    }
}

// ---------------- K2: fused normalize + QKV GEMM (wmma) ----------------
__global__ __launch_bounds__(256) void k_qkv(const float* __restrict__ x,
                                             const float* __restrict__ qkvb) {
    extern __shared__ char sm[];
    __nv_bfloat16* As = (__nv_bfloat16*)sm;
    __nv_bfloat16* Bs = As + 128*LDH;
    float*         Cs = (float*)(Bs + 128*LDH);
    const int nt = blockIdx.x, b = blockIdx.y, tid = threadIdx.x;
    const int nbase = nt*128;

    {
        int c = tid >> 1, nh = tid & 1;
        const float4* xp = (const float4*)(x + ((size_t)(b*CC) + c)*NN + nbase + nh*64);
        float sc = d_scl[b*CC + c], sh = d_sht[b*CC + c];
        #pragma unroll
        for (int i = 0; i < 16; i++) {
            float4 v = xp[i];
            int n = nh*64 + i*4;
            As[(n+0)*LDH + c] = __float2bfloat16(v.x*sc + sh);
            As[(n+1)*LDH + c] = __float2bfloat16(v.y*sc + sh);
            As[(n+2)*LDH + c] = __float2bfloat16(v.z*sc + sh);
            As[(n+3)*LDH + c] = __float2bfloat16(v.w*sc + sh);
        }
    }

    const int w = tid >> 5, wr = w >> 1, wc = w & 1;
    for (int ot = 0; ot < 3; ot++) {
        __syncthreads();
        {
            int o = tid >> 1, ch = tid & 1;
            const uint2* wp = (const uint2*)(d_wqkv + (ot*128 + o)*CC + ch*64);
            uint2* dp = (uint2*)(Bs + o*LDH + ch*64);
            #pragma unroll
            for (int i = 0; i < 16; i++) dp[i] = wp[i];
        }
        __syncthreads();
        #pragma unroll
        for (int i = 0; i < 2; i++) {
            FragC acc[4];
            #pragma unroll
            for (int jj = 0; jj < 4; jj++) wmma::fill_fragment(acc[jj], 0.f);
            #pragma unroll
            for (int k = 0; k < 8; k++) {
                FragA a; wmma::load_matrix_sync(a, As + (wr*32 + i*16)*LDH + k*16, LDH);
                #pragma unroll
                for (int jj = 0; jj < 4; jj++) {
                    FragBc bfr; wmma::load_matrix_sync(bfr, Bs + (wc*64 + jj*16)*LDH + k*16, LDH);
                    wmma::mma_sync(acc[jj], a, bfr, acc[jj]);
                }
            }
            #pragma unroll
            for (int jj = 0; jj < 4; jj++)
                wmma::store_matrix_sync(Cs + (wr*32 + i*16)*LDF + wc*64 + jj*16, acc[jj], LDF, wmma::mem_row_major);
        }
        __syncthreads();
        __nv_bfloat16* dst = (ot == 0) ? d_q : (ot == 1) ? d_k : d_v;
        {
            int n = tid >> 1, oh = tid & 1;
            __nv_bfloat16* op = dst + ((size_t)(b*NN) + nbase + n)*CC + oh*64;
            const float* cp = Cs + n*LDF + oh*64;
            const float* bp = qkvb + ot*128 + oh*64;
            #pragma unroll
            for (int i = 0; i < 64; i++) op[i] = __float2bfloat16(cp[i] + bp[i]);
        }
    }
}

// ---------------- K3: attention — register FA2 on mma.m16n8k16 ----------------
// CTA: 256 thr (8 warps), q-tile 128 (16 rows/warp), kv-tile 64, double-buffered cp.async.
// smem: sQ 32KB | sK0 16KB | sK1 16KB | sV0 16KB | sV1 16KB = 96KB.
// S accumulators live in registers; exp'd S repacked in-register as PV A-operand.

__device__ __forceinline__ void load_tile64(uint32_t sbase, const __nv_bfloat16* g, int tid) {
    // 64 rows x 128 cols bf16 = 1024 16B-chunks; 4 per thread; swizzle chunk ^= row&7
    #pragma unroll
    for (int j = 0; j < 4; j++) {
        int id = tid + 256*j;
        int row = id >> 4, c = id & 15;
        cpa16(sbase + row*256 + ((c ^ (row & 7)) << 4), g + row*CC + c*8);
    }
}

__global__ __launch_bounds__(256) void k_attn() {
    extern __shared__ char sm[];
    const int tid = threadIdx.x, lane = tid & 31, w = tid >> 5;
    const int qt = blockIdx.x, b = blockIdx.y;
    const uint32_t sb = smem_u32(sm);
    const uint32_t sQ = sb;
    const uint32_t sK[2] = { sb + 32768, sb + 49152 };
    const uint32_t sV[2] = { sb + 65536, sb + 81920 };

    const __nv_bfloat16* gq = d_q + ((size_t)(b*NN) + qt*128)*CC;
    const __nv_bfloat16* gk = d_k + (size_t)(b*NN)*CC;
    const __nv_bfloat16* gv = d_v + (size_t)(b*NN)*CC;

    // ---- prologue loads: Q + tile0 (group0), tile1 (group1) ----
    #pragma unroll
    for (int j = 0; j < 8; j++) {     // Q: 128x128 bf16 = 2048 chunks
        int id = tid + 256*j;
        int row = id >> 4, c = id & 15;
        cpa16(sQ + row*256 + ((c ^ (row & 7)) << 4), gq + row*CC + c*8);
    }
    load_tile64(sK[0], gk, tid);
    load_tile64(sV[0], gv, tid);
    CP_COMMIT();
    load_tile64(sK[1], gk + (size_t)64*CC, tid);
    load_tile64(sV[1], gv + (size_t)64*CC, tid);
    CP_COMMIT();

    const int r8 = lane & 7;            // row-within-8
    const int hs = (lane >> 3) & 1;     // tile half-select
    const int q16 = lane >> 4;          // chunk select

    CP_WAIT(1);                          // Q + tile0 resident
    __syncthreads();

    // ---- Q fragments (A-operand, row-major), k-frag kb covers d[16kb,16kb+16) ----
    uint32_t qf[8][4];
    #pragma unroll
    for (int kb = 0; kb < 8; kb++) {
        int row = w*16 + hs*8 + r8;
        int ch = 2*kb + q16;
        ldsm4(qf[kb], sQ + row*256 + ((ch ^ r8) << 4));
    }

    float o[16][4];
    #pragma unroll
    for (int nb = 0; nb < 16; nb++)
        #pragma unroll
        for (int e = 0; e < 4; e++) o[nb][e] = 0.f;
    float l0 = 0.f, l1 = 0.f;
    const float sl2e = 0.12751744f;     // (1/sqrt(128)) * log2(e)

    #pragma unroll 1
    for (int it = 0; it < 64; it++) {
        const int bi = it & 1;
        if (it > 0) { CP_WAIT(1); __syncthreads(); }

        // ---- S = Q K^T (this warp's 16 rows x 64 kv) ----
        float sc[8][4];
        #pragma unroll
        for (int nb = 0; nb < 8; nb++) {
            #pragma unroll
            for (int e = 0; e < 4; e++) sc[nb][e] = 0.f;
            #pragma unroll
            for (int kb2 = 0; kb2 < 4; kb2++) {
                uint32_t kf[4];
                int row = nb*8 + r8;
                int ch = 4*kb2 + (lane >> 3);
                ldsm4(kf, sK[bi] + row*256 + ((ch ^ r8) << 4));
                mma16816(sc[nb], qf[2*kb2],     kf);
                mma16816(sc[nb], qf[2*kb2 + 1], kf + 2);
            }
        }

        // ---- exp (no-max: |s*scale| bounded), row-sum partials, pack P ----
        #pragma unroll
        for (int nb = 0; nb < 8; nb++) {
            sc[nb][0] = ex2f(sc[nb][0]*sl2e);
            sc[nb][1] = ex2f(sc[nb][1]*sl2e);
            sc[nb][2] = ex2f(sc[nb][2]*sl2e);
            sc[nb][3] = ex2f(sc[nb][3]*sl2e);
            l0 += sc[nb][0] + sc[nb][1];
            l1 += sc[nb][2] + sc[nb][3];
        }
        uint32_t pk[4][4];
        #pragma unroll
        for (int kb = 0; kb < 4; kb++) {
            pk[kb][0] = packbf2(sc[2*kb][0],   sc[2*kb][1]);
            pk[kb][1] = packbf2(sc[2*kb][2],   sc[2*kb][3]);
            pk[kb][2] = packbf2(sc[2*kb+1][0], sc[2*kb+1][1]);
            pk[kb][3] = packbf2(sc[2*kb+1][2], sc[2*kb+1][3]);
        }

        // ---- O += P V ----
        #pragma unroll
        for (int nb2 = 0; nb2 < 8; nb2++) {
            #pragma unroll
            for (int kb = 0; kb < 4; kb++) {
                uint32_t vf[4];
                int row = kb*16 + hs*8 + r8;
                int ch = 2*nb2 + q16;
                ldsm4t(vf, sV[bi] + row*256 + ((ch ^ r8) << 4));
                mma16816(o[2*nb2],     pk[kb], vf);
                mma16816(o[2*nb2 + 1], pk[kb], vf + 2);
            }
        }

        __syncthreads();   // all warps done reading buf bi
        if (it + 2 < 64) {
            load_tile64(sK[bi], gk + (size_t)(it + 2)*64*CC, tid);
            load_tile64(sV[bi], gv + (size_t)(it + 2)*64*CC, tid);
        }
        CP_COMMIT();
    }

    // ---- finalize: quad-reduce row sums, normalize, store ----
    l0 += __shfl_xor_sync(0xffffffffu, l0, 1);
    l0 += __shfl_xor_sync(0xffffffffu, l0, 2);
    l1 += __shfl_xor_sync(0xffffffffu, l1, 1);
    l1 += __shfl_xor_sync(0xffffffffu, l1, 2);
    const float i0 = 1.f / l0, i1 = 1.f / l1;

    const int g = lane >> 2, c0 = (lane & 3)*2;
    __nv_bfloat16* ob = d_o + ((size_t)(b*NN) + qt*128 + w*16)*CC;
    #pragma unroll
    for (int nb = 0; nb < 16; nb++) {
        uint32_t p0 = packbf2(o[nb][0]*i0, o[nb][1]*i0);
        uint32_t p1 = packbf2(o[nb][2]*i1, o[nb][3]*i1);
        *(uint32_t*)(ob + (size_t)g*CC       + nb*8 + c0) = p0;
        *(uint32_t*)(ob + (size_t)(g + 8)*CC + nb*8 + c0) = p1;
    }
}

// ---------------- K4: proj GEMM + bias + residual (wmma) ----------------
__global__ __launch_bounds__(256) void k_proj(const float* __restrict__ x,
                                              const float* __restrict__ projb,
                                              float* __restrict__ out) {
    extern __shared__ char sm[];
    __nv_bfloat16* As = (__nv_bfloat16*)sm;
    __nv_bfloat16* Bs = As + 128*LDH;
    float*         Cs = (float*)(Bs + 128*LDH);
    const int nt = blockIdx.x, b = blockIdx.y, tid = threadIdx.x;
    const int nbase = nt*128;

    {
        const uint2* ag = (const uint2*)(d_o + ((size_t)(b*NN) + nbase)*CC);
        for (int i = tid; i < 128*32; i += 256) {
            int r = i >> 5, cv = i & 31;
            *(uint2*)&As[r*LDH + cv*4] = ag[r*32 + cv];
        }
    }
    {
        int o = tid >> 1, ch = tid & 1;
        const uint2* wp = (const uint2*)(d_wproj + o*CC + ch*64);
        uint2* dp = (uint2*)(Bs + o*LDH + ch*64);
        #pragma unroll
        for (int i = 0; i < 16; i++) dp[i] = wp[i];
    }
    __syncthreads();

    const int w = tid >> 5, wr = w >> 1, wc = w & 1;
    #pragma unroll
    for (int i = 0; i < 2; i++) {
        FragC acc[4];
        #pragma unroll
        for (int jj = 0; jj < 4; jj++) wmma::fill_fragment(acc[jj], 0.f);
        #pragma unroll
        for (int k = 0; k < 8; k++) {
            FragA a; wmma::load_matrix_sync(a, As + (wr*32 + i*16)*LDH + k*16, LDH);
            #pragma unroll
            for (int jj = 0; jj < 4; jj++) {
                FragBc bfr; wmma::load_matrix_sync(bfr, Bs + (wc*64 + jj*16)*LDH + k*16, LDH);
                wmma::mma_sync(acc[jj], a, bfr, acc[jj]);
            }
        }
        #pragma unroll
        for (int jj = 0; jj < 4; jj++)
            wmma::store_matrix_sync(Cs + (wr*32 + i*16)*LDF + wc*64 + jj*16, acc[jj], LDF, wmma::mem_row_major);
    }
    __syncthreads();
    {
        int c = tid >> 1, nh = tid & 1;
        const float* xp = x + ((size_t)(b*CC) + c)*NN + nbase + nh*64;
        float* op = out + ((size_t)(b*CC) + c)*NN + nbase + nh*64;
        float pb = projb[c];
        #pragma unroll
        for (int i = 0; i < 64; i++)
            op[i] = xp[i] + pb + Cs[(nh*64 + i)*LDF + c];
    }
}

// ---------------- launcher ----------------
extern "C" void kernel_launch(void* const* d_in, const int* in_sizes, int n_in,
                              void* d_out, int out_size) {
    const float* x     = (const float*)d_in[0];
    const float* nw    = (const float*)d_in[1];
    const float* nb    = (const float*)d_in[2];
    const float* qkvw  = (const float*)d_in[3];
    const float* qkvb  = (const float*)d_in[4];
    const float* projw = (const float*)d_in[5];
    const float* projb = (const float*)d_in[6];
    float* out = (float*)d_out;

    const int SM_GEMM = 2*128*LDH*2 + 128*LDF*4;     // 137216
    const int SM_ATTN = 32768 + 4*16384;             // 98304

    cudaFuncSetAttribute(k_qkv,  cudaFuncAttributeMaxDynamicSharedMemorySize, SM_GEMM);
    cudaFuncSetAttribute(k_attn, cudaFuncAttributeMaxDynamicSharedMemorySize, SM_ATTN);
    cudaFuncSetAttribute(k_proj, cudaFuncAttributeMaxDynamicSharedMemorySize, SM_GEMM);

    k_convert<<<192, 256>>>(qkvw, projw);
    k_gnstats<<<32, 256>>>(x, nw, nb);
    k_qkv<<<dim3(32, BB), 256, SM_GEMM>>>(x, qkvb);
    k_attn<<<dim3(32, BB), 256, SM_ATTN>>>();
    k_proj<<<dim3(32, BB), 256, SM_GEMM>>>(x, projb, out);
}